// round 3
// baseline (speedup 1.0000x reference)
#include <cuda_runtime.h>
#include <cuda_bf16.h>
#include <cstdint>

// ============================================================
// AWQLinear, baseline-ISA build (harness targets plain sm_103 —
// no tcgen05/'a' features). tf32 mma.sync GEMM:
//   y[m,o] = sum_k (x[m,k]/alpha[k]) * (q[o,k]-8)*sc[o,k/32] + bias[o]
// M=4096, N=11008, K=4096.
// Prep kernels write operands in mma-fragment-major order so the
// GEMM does linear cp.async copies + conflict-free LDS.128 only.
// ============================================================

#define IN_F   4096
#define OUT_F  11008
#define MROWS  4096
#define NKT    128          // K / 32
#define TM     256
#define TN     128
#define STAGES 3
// per (m_blk, kt): 4 ksteps x 16 mtiles x 32 thr x 4 slots = 8192 floats (32KB)
// per (n_blk, kt): 4 ksteps x  8 pairs  x 32 thr x 4 slots = 4096 floats (16KB)
#define A_BLK  8192
#define B_BLK  4096
#define STAGE_FLTS (A_BLK + B_BLK)          // 12288 floats = 48KB
#define SMEM_BYTES (STAGES * STAGE_FLTS * 4)

__device__ float g_A[(size_t)(MROWS / TM) * NKT * A_BLK];   // 64 MB
__device__ float g_B[(size_t)(OUT_F / TN) * NKT * B_BLK];   // 180 MB

// ---------------- helpers ----------------
__device__ __forceinline__ uint32_t smem_u32(const void* p) {
    uint32_t a;
    asm("{ .reg .u64 t; cvta.to.shared.u64 t, %1; cvt.u32.u64 %0, t; }"
        : "=r"(a) : "l"(p));
    return a;
}

__device__ __forceinline__ float tf32_rna(float v) {
    uint32_t r;
    asm("cvt.rna.tf32.f32 %0, %1;" : "=r"(r) : "f"(v));
    return __uint_as_float(r);
}

__device__ __forceinline__ void cp16(uint32_t dst, const void* src) {
    asm volatile("cp.async.cg.shared.global [%0], [%1], 16;"
                 :: "r"(dst), "l"(src) : "memory");
}
#define CP_COMMIT() asm volatile("cp.async.commit_group;" ::: "memory")
#define CP_WAIT1()  asm volatile("cp.async.wait_group 1;" ::: "memory")

__device__ __forceinline__ void mma_tf32(float4& d, const float4 a,
                                         const float b0, const float b1) {
    asm("mma.sync.aligned.m16n8k8.row.col.f32.tf32.tf32.f32 "
        "{%0,%1,%2,%3}, {%4,%5,%6,%7}, {%8,%9}, {%0,%1,%2,%3};"
        : "+f"(d.x), "+f"(d.y), "+f"(d.z), "+f"(d.w)
        : "r"(__float_as_uint(a.x)), "r"(__float_as_uint(a.y)),
          "r"(__float_as_uint(a.z)), "r"(__float_as_uint(a.w)),
          "r"(__float_as_uint(b0)),  "r"(__float_as_uint(b1)));
}

// ---------------- prep: pack operands fragment-major ----------------
// m16n8k8 tf32 A frag: a0=(r,c) a1=(r+8,c) a2=(r,c+4) a3=(r+8,c+4),
//   r = t/4, c = t%4  (within a 16x8 tile)
__global__ void prep_x_kernel(const float* __restrict__ x,
                              const float* __restrict__ alpha) {
    int i = blockIdx.x * 256 + threadIdx.x;       // < MROWS*IN_F
    int m = i >> 12, k = i & 4095;
    float v = x[i] / alpha[k];
    int mb = m >> 8, r = m & 255;
    int itile = r >> 4, tr = r & 15;
    int kt = k >> 5, ks = (k >> 3) & 3, c = k & 7;
    int th   = ((tr & 7) << 2) | (c & 3);
    int slot = ((c >> 2) << 1) | (tr >> 3);
    size_t off = ((size_t)mb * NKT + kt) * A_BLK
               + ((((ks << 4) + itile) << 5) + th) * 4 + slot;
    g_A[off] = tf32_rna(v);
}

// B frag (k8n8 col-major): b0=(kk,cn8) kk=t%4, b1: kk=t%4+4, cn8=t/4.
// Two adjacent n8 tiles packed per 16B: [b0(j),b1(j),b0(j+1),b1(j+1)]
__global__ void prep_w_kernel(const int* __restrict__ q,
                              const float* __restrict__ sc) {
    int i = blockIdx.x * 256 + threadIdx.x;       // < OUT_F*IN_F
    int o = i >> 12, k = i & 4095;
    float w = (float)(q[i] - 8) * sc[(o << 7) + (k >> 5)];
    int nb = o >> 7, cn = o & 127;
    int jp = cn >> 4, jodd = (cn >> 3) & 1, cn8 = cn & 7;
    int kt = k >> 5, ks = (k >> 3) & 3, kk = k & 7;
    int th   = (cn8 << 2) | (kk & 3);
    int slot = (jodd << 1) | (kk >> 2);
    size_t off = ((size_t)nb * NKT + kt) * B_BLK
               + ((((ks << 3) + jp) << 5) + th) * 4 + slot;
    g_B[off] = tf32_rna(w);
}

// ---------------- GEMM: 256x128 CTA, 8 warps (4x2) of 64x64 ----------------
__global__ __launch_bounds__(256, 1)
void awq_gemm_kernel(const float* __restrict__ bias, float* __restrict__ out) {
    extern __shared__ float sm[];
    const uint32_t sbase = smem_u32(sm);
    int tid = threadIdx.x, wid = tid >> 5, t = tid & 31;
    int wm = wid & 3, wn = wid >> 2;              // 4 x 2 warp grid
    int mt = blockIdx.x, nt = blockIdx.y;

    const float* gA = g_A + (size_t)mt * NKT * A_BLK;
    const float* gB = g_B + (size_t)nt * NKT * B_BLK;

    auto copy_stage = [&](int kt, int p) {
        uint32_t sA = sbase + (uint32_t)p * (STAGE_FLTS * 4);
        const float* srcA = gA + (size_t)kt * A_BLK;
#pragma unroll
        for (int r = 0; r < 8; r++)
            cp16(sA + (uint32_t)(tid + r * 256) * 16, srcA + (tid + r * 256) * 4);
        uint32_t sB = sA + A_BLK * 4;
        const float* srcB = gB + (size_t)kt * B_BLK;
#pragma unroll
        for (int r = 0; r < 4; r++)
            cp16(sB + (uint32_t)(tid + r * 256) * 16, srcB + (tid + r * 256) * 4);
    };

    copy_stage(0, 0); CP_COMMIT();
    copy_stage(1, 1); CP_COMMIT();

    float4 acc[4][8];
#pragma unroll
    for (int i = 0; i < 4; i++)
#pragma unroll
        for (int j = 0; j < 8; j++) acc[i][j] = make_float4(0.f, 0.f, 0.f, 0.f);

    for (int kt = 0; kt < NKT; kt++) {
        int p = kt % STAGES;
        CP_WAIT1();
        __syncthreads();
        if (kt + 2 < NKT) copy_stage(kt + 2, (kt + 2) % STAGES);
        CP_COMMIT();                               // empty group on tail keeps count

        const float* As = sm + p * STAGE_FLTS;
        const float* Bs = As + A_BLK;
#pragma unroll
        for (int s = 0; s < 4; s++) {
            float4 a[4], b[4];
#pragma unroll
            for (int il = 0; il < 4; il++)
                a[il] = *(const float4*)(As + ((((s << 4) + (wm << 2) + il) << 5) + t) * 4);
#pragma unroll
            for (int pl = 0; pl < 4; pl++)
                b[pl] = *(const float4*)(Bs + ((((s << 3) + (wn << 2) + pl) << 5) + t) * 4);
#pragma unroll
            for (int il = 0; il < 4; il++) {
#pragma unroll
                for (int j = 0; j < 8; j++) {
                    const float4& bp = b[j >> 1];
                    if (j & 1) mma_tf32(acc[il][j], a[il], bp.z, bp.w);
                    else       mma_tf32(acc[il][j], a[il], bp.x, bp.y);
                }
            }
        }
    }

    // ---- epilogue: regs -> +bias -> gmem ----
    int quad = t >> 2, tq = t & 3;
    int row_base = mt * TM + wm * 64;
    int col_base = nt * TN + wn * 64;
#pragma unroll
    for (int il = 0; il < 4; il++) {
        int r0 = row_base + il * 16 + quad;
        float* o0 = out + (size_t)r0 * OUT_F;
        float* o1 = o0 + (size_t)8 * OUT_F;
#pragma unroll
        for (int j = 0; j < 8; j++) {
            int c = col_base + j * 8 + tq * 2;
            float b0 = bias[c], b1 = bias[c + 1];
            float4 v = acc[il][j];
            *(float2*)(o0 + c) = make_float2(v.x + b0, v.y + b1);
            *(float2*)(o1 + c) = make_float2(v.z + b0, v.w + b1);
        }
    }
}

// ---------------- launch ----------------
extern "C" void kernel_launch(void* const* d_in, const int* in_sizes, int n_in,
                              void* d_out, int out_size) {
    const float* x     = (const float*)d_in[0];   // [2,2048,4096] f32
    const int*   qw    = (const int*)d_in[1];     // [11008,4096] int32 codes
    const float* sc    = (const float*)d_in[2];   // [11008,128] f32
    const float* alpha = (const float*)d_in[3];   // [4096] f32
    const float* bias  = (const float*)d_in[4];   // [11008] f32
    float* out = (float*)d_out;                   // [4096,11008] f32

    cudaFuncSetAttribute(awq_gemm_kernel,
                         cudaFuncAttributeMaxDynamicSharedMemorySize, SMEM_BYTES);

    prep_x_kernel<<<(MROWS * IN_F) / 256, 256>>>(x, alpha);
    prep_w_kernel<<<(OUT_F * IN_F) / 256, 256>>>(qw, sc);

    dim3 grid(MROWS / TM, OUT_F / TN);            // (16, 86)
    awq_gemm_kernel<<<grid, 256, SMEM_BYTES>>>(bias, out);
}

// round 4
// speedup vs baseline: 1.8205x; 1.8205x over previous
#include <cuda_runtime.h>
#include <cuda_fp16.h>
#include <cstdint>

// ============================================================
// AWQLinear via fp16 mma.sync (same 10-bit mantissa as tf32,
// 2x FLOP/instr): y = (x/alpha) @ W_hat^T + bias
// M=4096, N=11008, K=4096. Operands pre-packed fragment-major
// so the GEMM is linear cp.async + conflict-free LDS.128 only.
// ============================================================

#define IN_F   4096
#define OUT_F  11008
#define MROWS  4096
#define NKT    64            // K / 64 (64-k chunk per stage)
#define TM     256
#define TN     128
#define STAGES 3
// per (mb,kt): 4 ksteps x 16 mtiles x 32 thr x 4 b32 = 8192 b32 (32KB)
// per (nb,kt): 4 ksteps x  8 pairs  x 32 thr x 4 b32 = 4096 b32 (16KB)
#define A_BLK_B32 8192
#define B_BLK_B32 4096
#define STAGE_BYTES ((A_BLK_B32 + B_BLK_B32) * 4)     // 48KB
#define SMEM_BYTES (STAGES * STAGE_BYTES)             // 144KB

__device__ __half2 g_A[(size_t)(MROWS / TM) * NKT * A_BLK_B32];   // 32MB
__device__ __half2 g_B[(size_t)(OUT_F / TN) * NKT * B_BLK_B32];   // 90MB

// ---------------- helpers ----------------
__device__ __forceinline__ uint32_t smem_u32(const void* p) {
    uint32_t a;
    asm("{ .reg .u64 t; cvta.to.shared.u64 t, %1; cvt.u32.u64 %0, t; }"
        : "=r"(a) : "l"(p));
    return a;
}

__device__ __forceinline__ void cp16(uint32_t dst, const void* src) {
    asm volatile("cp.async.cg.shared.global [%0], [%1], 16;"
                 :: "r"(dst), "l"(src) : "memory");
}
#define CP_COMMIT() asm volatile("cp.async.commit_group;" ::: "memory")
#define CP_WAIT1()  asm volatile("cp.async.wait_group 1;" ::: "memory")

__device__ __forceinline__ void mma_f16(float4& d, const uint4 a,
                                        const uint32_t b0, const uint32_t b1) {
    asm("mma.sync.aligned.m16n8k16.row.col.f32.f16.f16.f32 "
        "{%0,%1,%2,%3}, {%4,%5,%6,%7}, {%8,%9}, {%0,%1,%2,%3};"
        : "+f"(d.x), "+f"(d.y), "+f"(d.z), "+f"(d.w)
        : "r"(a.x), "r"(a.y), "r"(a.z), "r"(a.w), "r"(b0), "r"(b1));
}

// ---------------- prep: pack operands fragment-major (fp16) ----------------
// m16n8k16 A frag (row-major 16x16): reg r in {a0..a3}:
//   a0:(row=t/4, k=(t%4)*2+{0,1})  a1:(row+8, same k)
//   a2:(row, k+8)                  a3:(row+8, k+8)
// Each thread packs 2 adjacent k (one half2 = one b32 slot).
__global__ void prep_x_kernel(const float* __restrict__ x,
                              const float* __restrict__ alpha) {
    int i2 = blockIdx.x * 256 + threadIdx.x;      // pair idx < MROWS*IN_F/2
    int m = i2 >> 11, k = (i2 & 2047) << 1;
    float a0 = alpha[k], a1 = alpha[k + 1];
    const float* xr = x + ((size_t)m << 12) + k;
    __half2 v = __floats2half2_rn(xr[0] / a0, xr[1] / a1);

    int mb = m >> 8, r = m & 255;
    int itile = r >> 4, tr = r & 15;
    int kt = k >> 6, kc = k & 63, s = kc >> 4, kk = kc & 15;
    int reg = ((kk >> 3) << 1) | (tr >> 3);
    int th  = ((tr & 7) << 2) | ((kk >> 1) & 3);
    size_t off = ((size_t)(mb * NKT + kt)) * A_BLK_B32
               + ((((s << 4) + itile) << 5) + th) * 4 + reg;
    g_A[off] = v;
}

// B frag (col-major n8 x k16): b0:(k=(t%4)*2+{0,1}, n=t/4), b1:(k+8, n).
// Two adjacent n8-tiles per 16B: slots [b0(j0), b1(j0), b0(j1), b1(j1)].
__global__ void prep_w_kernel(const int* __restrict__ q,
                              const float* __restrict__ sc) {
    int i2 = blockIdx.x * 256 + threadIdx.x;      // pair idx < OUT_F*IN_F/2
    int o = i2 >> 11, k = (i2 & 2047) << 1;
    float s0 = sc[(o << 7) + (k >> 5)];
    const int* qr = q + ((size_t)o << 12) + k;
    __half2 v = __floats2half2_rn((float)(qr[0] - 8) * s0,
                                  (float)(qr[1] - 8) * s0);

    int nb = o >> 7, cn = o & 127;
    int jp = cn >> 4, jodd = (cn >> 3) & 1, n8 = cn & 7;
    int kt = k >> 6, kc = k & 63, s = kc >> 4, kk = kc & 15;
    int th   = (n8 << 2) | ((kk >> 1) & 3);
    int slot = (jodd << 1) | (kk >> 3);
    size_t off = ((size_t)(nb * NKT + kt)) * B_BLK_B32
               + ((((s << 3) + jp) << 5) + th) * 4 + slot;
    g_B[off] = v;
}

// ---------------- GEMM: 256x128 CTA, 8 warps (4x2) of 64x64 ----------------
__global__ __launch_bounds__(256, 1)
void awq_gemm_kernel(const float* __restrict__ bias, float* __restrict__ out) {
    extern __shared__ char sm[];
    const uint32_t sbase = smem_u32(sm);
    int tid = threadIdx.x, wid = tid >> 5, t = tid & 31;
    int wm = wid & 3, wn = wid >> 2;              // 4 x 2 warp grid
    int mt = blockIdx.x, nt = blockIdx.y;

    const char* gA = (const char*)(g_A + (size_t)mt * NKT * A_BLK_B32);
    const char* gB = (const char*)(g_B + (size_t)nt * NKT * B_BLK_B32);

    auto copy_stage = [&](int kt, int p) {
        uint32_t sA = sbase + (uint32_t)p * STAGE_BYTES;
        const char* srcA = gA + (size_t)kt * (A_BLK_B32 * 4);
#pragma unroll
        for (int r = 0; r < 8; r++)               // 32KB A
            cp16(sA + (uint32_t)(tid + r * 256) * 16, srcA + (tid + r * 256) * 16);
        uint32_t sB = sA + A_BLK_B32 * 4;
        const char* srcB = gB + (size_t)kt * (B_BLK_B32 * 4);
#pragma unroll
        for (int r = 0; r < 4; r++)               // 16KB B
            cp16(sB + (uint32_t)(tid + r * 256) * 16, srcB + (tid + r * 256) * 16);
    };

    copy_stage(0, 0); CP_COMMIT();
    copy_stage(1, 1); CP_COMMIT();

    float4 acc[4][8];
#pragma unroll
    for (int i = 0; i < 4; i++)
#pragma unroll
        for (int j = 0; j < 8; j++) acc[i][j] = make_float4(0.f, 0.f, 0.f, 0.f);

    for (int kt = 0; kt < NKT; kt++) {
        int p = kt % STAGES;
        CP_WAIT1();
        __syncthreads();
        if (kt + 2 < NKT) copy_stage(kt + 2, (kt + 2) % STAGES);
        CP_COMMIT();

        const char* As = sm + p * STAGE_BYTES;
        const char* Bs = As + A_BLK_B32 * 4;
#pragma unroll
        for (int s = 0; s < 4; s++) {
            uint4 a[4], b[4];
#pragma unroll
            for (int il = 0; il < 4; il++)
                a[il] = *(const uint4*)(As + (size_t)(((((s << 4) + (wm << 2) + il) << 5) + t) * 16));
#pragma unroll
            for (int pl = 0; pl < 4; pl++)
                b[pl] = *(const uint4*)(Bs + (size_t)(((((s << 3) + (wn << 2) + pl) << 5) + t) * 16));
#pragma unroll
            for (int il = 0; il < 4; il++) {
#pragma unroll
                for (int j = 0; j < 8; j++) {
                    const uint4& bp = b[j >> 1];
                    if (j & 1) mma_f16(acc[il][j], a[il], bp.z, bp.w);
                    else       mma_f16(acc[il][j], a[il], bp.x, bp.y);
                }
            }
        }
    }

    // ---- epilogue: regs -> +bias -> gmem ----
    int quad = t >> 2, tq = t & 3;
    int row_base = mt * TM + wm * 64;
    int col_base = nt * TN + wn * 64;
#pragma unroll
    for (int il = 0; il < 4; il++) {
        int r0 = row_base + il * 16 + quad;
        float* o0 = out + (size_t)r0 * OUT_F;
        float* o1 = o0 + (size_t)8 * OUT_F;
#pragma unroll
        for (int j = 0; j < 8; j++) {
            int c = col_base + j * 8 + tq * 2;
            float b0 = bias[c], b1 = bias[c + 1];
            float4 v = acc[il][j];
            *(float2*)(o0 + c) = make_float2(v.x + b0, v.y + b1);
            *(float2*)(o1 + c) = make_float2(v.z + b0, v.w + b1);
        }
    }
}

// ---------------- launch ----------------
extern "C" void kernel_launch(void* const* d_in, const int* in_sizes, int n_in,
                              void* d_out, int out_size) {
    const float* x     = (const float*)d_in[0];   // [2,2048,4096] f32
    const int*   qw    = (const int*)d_in[1];     // [11008,4096] int32 codes
    const float* sc    = (const float*)d_in[2];   // [11008,128] f32
    const float* alpha = (const float*)d_in[3];   // [4096] f32
    const float* bias  = (const float*)d_in[4];   // [11008] f32
    float* out = (float*)d_out;                   // [4096,11008] f32

    cudaFuncSetAttribute(awq_gemm_kernel,
                         cudaFuncAttributeMaxDynamicSharedMemorySize, SMEM_BYTES);

    prep_x_kernel<<<(MROWS * IN_F) / 512, 256>>>(x, alpha);
    prep_w_kernel<<<(OUT_F * IN_F) / 512, 256>>>(qw, sc);

    dim3 grid(MROWS / TM, OUT_F / TN);            // (16, 86)
    awq_gemm_kernel<<<grid, 256, SMEM_BYTES>>>(bias, out);
}

// round 5
// speedup vs baseline: 1.9926x; 1.0946x over previous
#include <cuda_runtime.h>
#include <cuda_fp16.h>
#include <cstdint>

// ============================================================
// AWQLinear via fp16 mma.sync m16n8k16 (same mantissa as tf32).
// y = (x/alpha) @ W_hat^T + bias, M=4096 N=11008 K=4096.
// Operands pre-packed fragment-major; GEMM: 4-stage cp.async
// pipeline + double-buffered fragment regs.
// ============================================================

#define IN_F   4096
#define OUT_F  11008
#define MROWS  4096
#define NKT    64            // K / 64
#define TM     256
#define TN     128
#define STAGES 4
#define A_BLK_B32 8192       // 32KB per (mb,kt)
#define B_BLK_B32 4096       // 16KB per (nb,kt)
#define STAGE_BYTES ((A_BLK_B32 + B_BLK_B32) * 4)     // 48KB
#define SMEM_BYTES (STAGES * STAGE_BYTES)             // 192KB

__device__ __half2 g_A[(size_t)(MROWS / TM) * NKT * A_BLK_B32];   // 32MB
__device__ __half2 g_B[(size_t)(OUT_F / TN) * NKT * B_BLK_B32];   // 90MB

// ---------------- helpers ----------------
__device__ __forceinline__ uint32_t smem_u32(const void* p) {
    uint32_t a;
    asm("{ .reg .u64 t; cvta.to.shared.u64 t, %1; cvt.u32.u64 %0, t; }"
        : "=r"(a) : "l"(p));
    return a;
}
__device__ __forceinline__ void cp16(uint32_t dst, const void* src) {
    asm volatile("cp.async.cg.shared.global [%0], [%1], 16;"
                 :: "r"(dst), "l"(src) : "memory");
}
#define CP_COMMIT() asm volatile("cp.async.commit_group;" ::: "memory")
#define CP_WAIT2()  asm volatile("cp.async.wait_group 2;" ::: "memory")

__device__ __forceinline__ void mma_f16(float4& d, const uint4 a,
                                        const uint32_t b0, const uint32_t b1) {
    asm("mma.sync.aligned.m16n8k16.row.col.f32.f16.f16.f32 "
        "{%0,%1,%2,%3}, {%4,%5,%6,%7}, {%8,%9}, {%0,%1,%2,%3};"
        : "+f"(d.x), "+f"(d.y), "+f"(d.z), "+f"(d.w)
        : "r"(a.x), "r"(a.y), "r"(a.z), "r"(a.w), "r"(b0), "r"(b1));
}
__device__ __forceinline__ uint32_t h2u(__half2 h) { return *(uint32_t*)&h; }

// ---------------- prep: fragment-major pack, 1 thread = 1 16B chunk ------
// A chunk c within (mb,kt) block: c = ((s*16+itile)*32 + th), th = (tr&7)*4+c2
// slots: [ (row,k01), (row+8,k01), (row,k01+8), (row+8,k01+8) ]
__global__ void prep_x_kernel(const float* __restrict__ x,
                              const float* __restrict__ alpha) {
    int j = blockIdx.x * 256 + threadIdx.x;       // < MROWS*IN_F/8
    int blk = j >> 11, c = j & 2047;
    int th = c & 31, it = (c >> 5) & 15, s = c >> 9;
    int mb = blk >> 6, kt = blk & 63;
    int row0 = (mb << 8) + (it << 4) + (th >> 2);
    int k0 = (kt << 6) + (s << 4) + ((th & 3) << 1);
    const float* x0 = x + ((size_t)row0 << 12) + k0;
    const float* x8 = x0 + (8 << 12);
    float ia0 = 1.0f / alpha[k0],     ia1 = 1.0f / alpha[k0 + 1];
    float ia8 = 1.0f / alpha[k0 + 8], ia9 = 1.0f / alpha[k0 + 9];
    float2 v00 = *(const float2*)(x0);
    float2 v10 = *(const float2*)(x8);
    float2 v08 = *(const float2*)(x0 + 8);
    float2 v18 = *(const float2*)(x8 + 8);
    uint4 o;
    o.x = h2u(__floats2half2_rn(v00.x * ia0, v00.y * ia1));
    o.y = h2u(__floats2half2_rn(v10.x * ia0, v10.y * ia1));
    o.z = h2u(__floats2half2_rn(v08.x * ia8, v08.y * ia9));
    o.w = h2u(__floats2half2_rn(v18.x * ia8, v18.y * ia9));
    *(uint4*)(g_A + (size_t)j * 4) = o;
}

// B chunk c within (nb,kt): c = ((s*8+jp)*32 + th), th = n8*4 + c2
// slots: [ (o0,k01), (o0,k01+8), (o0+8,k01), (o0+8,k01+8) ]
__global__ void prep_w_kernel(const int* __restrict__ q,
                              const float* __restrict__ sc) {
    int j = blockIdx.x * 256 + threadIdx.x;       // < OUT_F*IN_F/8
    int blk = j >> 10, c = j & 1023;
    int th = c & 31, jp = (c >> 5) & 7, s = c >> 8;
    int nb = blk >> 6, kt = blk & 63;
    int o0 = (nb << 7) + (jp << 4) + (th >> 2);
    int k0 = (kt << 6) + (s << 4) + ((th & 3) << 1);
    int sblk = (kt << 1) + (s >> 1);              // k-block of 32 (same for k0,k0+8)
    const int* q0 = q + ((size_t)o0 << 12) + k0;
    const int* q8 = q0 + (8 << 12);
    float s0 = sc[(o0 << 7) + sblk];
    float s1 = sc[((o0 + 8) << 7) + sblk];
    int2 a0 = *(const int2*)(q0);
    int2 a2 = *(const int2*)(q0 + 8);
    int2 b0 = *(const int2*)(q8);
    int2 b2 = *(const int2*)(q8 + 8);
    uint4 o;
    o.x = h2u(__floats2half2_rn((float)(a0.x - 8) * s0, (float)(a0.y - 8) * s0));
    o.y = h2u(__floats2half2_rn((float)(a2.x - 8) * s0, (float)(a2.y - 8) * s0));
    o.z = h2u(__floats2half2_rn((float)(b0.x - 8) * s1, (float)(b0.y - 8) * s1));
    o.w = h2u(__floats2half2_rn((float)(b2.x - 8) * s1, (float)(b2.y - 8) * s1));
    *(uint4*)(g_B + (size_t)j * 4) = o;
}

// ---------------- GEMM: 256x128 CTA, 8 warps (4x2) of 64x64 ----------------
__global__ __launch_bounds__(256, 1)
void awq_gemm_kernel(const float* __restrict__ bias, float* __restrict__ out) {
    extern __shared__ char sm[];
    const uint32_t sbase = smem_u32(sm);
    int tid = threadIdx.x, wid = tid >> 5, t = tid & 31;
    int wm = wid & 3, wn = wid >> 2;
    int mt = blockIdx.x, nt = blockIdx.y;

    const char* gA = (const char*)(g_A + (size_t)mt * NKT * A_BLK_B32);
    const char* gB = (const char*)(g_B + (size_t)nt * NKT * B_BLK_B32);

    auto copy_stage = [&](int kt, int p) {
        uint32_t sA = sbase + (uint32_t)p * STAGE_BYTES;
        const char* srcA = gA + (size_t)kt * (A_BLK_B32 * 4);
#pragma unroll
        for (int r = 0; r < 8; r++)
            cp16(sA + (uint32_t)(tid + r * 256) * 16, srcA + (tid + r * 256) * 16);
        uint32_t sB = sA + A_BLK_B32 * 4;
        const char* srcB = gB + (size_t)kt * (B_BLK_B32 * 4);
#pragma unroll
        for (int r = 0; r < 4; r++)
            cp16(sB + (uint32_t)(tid + r * 256) * 16, srcB + (tid + r * 256) * 16);
    };

    copy_stage(0, 0); CP_COMMIT();
    copy_stage(1, 1); CP_COMMIT();
    copy_stage(2, 2); CP_COMMIT();

    float4 acc[4][8];
#pragma unroll
    for (int i = 0; i < 4; i++)
#pragma unroll
        for (int jj = 0; jj < 8; jj++) acc[i][jj] = make_float4(0.f, 0.f, 0.f, 0.f);

    auto load_frag = [&](uint4* a, uint4* b, const char* As, const char* Bs, int s) {
#pragma unroll
        for (int il = 0; il < 4; il++)
            a[il] = *(const uint4*)(As + (size_t)(((((s << 4) + (wm << 2) + il) << 5) + t) * 16));
#pragma unroll
        for (int pl = 0; pl < 4; pl++)
            b[pl] = *(const uint4*)(Bs + (size_t)(((((s << 3) + (wn << 2) + pl) << 5) + t) * 16));
    };
    auto do_mma = [&](const uint4* a, const uint4* b) {
#pragma unroll
        for (int il = 0; il < 4; il++)
#pragma unroll
            for (int jj = 0; jj < 8; jj++) {
                const uint4& bp = b[jj >> 1];
                if (jj & 1) mma_f16(acc[il][jj], a[il], bp.z, bp.w);
                else        mma_f16(acc[il][jj], a[il], bp.x, bp.y);
            }
    };

    auto iter = [&](int kt, int p) {
        CP_WAIT2();
        __syncthreads();
        if (kt + 3 < NKT) copy_stage(kt + 3, (p + 3) & 3);
        CP_COMMIT();
        const char* As = sm + p * STAGE_BYTES;
        const char* Bs = As + A_BLK_B32 * 4;
        uint4 a[2][4], b[2][4];
        load_frag(a[0], b[0], As, Bs, 0);
#pragma unroll
        for (int s = 0; s < 4; s++) {
            int cur = s & 1;
            if (s < 3) load_frag(a[cur ^ 1], b[cur ^ 1], As, Bs, s + 1);
            do_mma(a[cur], b[cur]);
        }
    };

    for (int kt = 0; kt < NKT; kt += 4) {
        iter(kt + 0, 0);
        iter(kt + 1, 1);
        iter(kt + 2, 2);
        iter(kt + 3, 3);
    }

    // ---- epilogue ----
    int quad = t >> 2, tq = t & 3;
    int row_base = mt * TM + wm * 64;
    int col_base = nt * TN + wn * 64;
#pragma unroll
    for (int il = 0; il < 4; il++) {
        int r0 = row_base + il * 16 + quad;
        float* o0 = out + (size_t)r0 * OUT_F;
        float* o1 = o0 + (size_t)8 * OUT_F;
#pragma unroll
        for (int jj = 0; jj < 8; jj++) {
            int cc = col_base + jj * 8 + tq * 2;
            float b0 = bias[cc], b1 = bias[cc + 1];
            float4 v = acc[il][jj];
            *(float2*)(o0 + cc) = make_float2(v.x + b0, v.y + b1);
            *(float2*)(o1 + cc) = make_float2(v.z + b0, v.w + b1);
        }
    }
}

// ---------------- launch ----------------
extern "C" void kernel_launch(void* const* d_in, const int* in_sizes, int n_in,
                              void* d_out, int out_size) {
    const float* x     = (const float*)d_in[0];
    const int*   qw    = (const int*)d_in[1];
    const float* sc    = (const float*)d_in[2];
    const float* alpha = (const float*)d_in[3];
    const float* bias  = (const float*)d_in[4];
    float* out = (float*)d_out;

    cudaFuncSetAttribute(awq_gemm_kernel,
                         cudaFuncAttributeMaxDynamicSharedMemorySize, SMEM_BYTES);

    prep_x_kernel<<<(MROWS * IN_F) / 2048, 256>>>(x, alpha);
    prep_w_kernel<<<(OUT_F * IN_F) / 2048, 256>>>(qw, sc);

    dim3 grid(MROWS / TM, OUT_F / TN);            // (16, 86)
    awq_gemm_kernel<<<grid, 256, SMEM_BYTES>>>(bias, out);
}

// round 7
// speedup vs baseline: 2.3662x; 1.1875x over previous
#include <cuda_runtime.h>
#include <cuda_fp16.h>
#include <cstdint>

// ============================================================
// AWQLinear via fp16 mma.sync m16n8k16 (same mantissa as tf32).
// y = (x/alpha) @ W_hat^T + bias, M=4096 N=11008 K=4096.
// Fragment-major pre-pack; GEMM: 4-stage cp.async pipeline,
// double-buffered frags + cross-iter s0-fragment prefetch.
// Fragment loads are plain C++ derefs (barrier-ordered).
// ============================================================

#define IN_F   4096
#define OUT_F  11008
#define MROWS  4096
#define NKT    64            // K / 64
#define TM     256
#define TN     128
#define A_BLK_B32 8192       // 32KB per (mb,kt)
#define B_BLK_B32 4096       // 16KB per (nb,kt)
#define STAGE_BYTES ((A_BLK_B32 + B_BLK_B32) * 4)     // 48KB
#define SMEM_BYTES (4 * STAGE_BYTES)                  // 192KB
#define A_KT_BYTES (A_BLK_B32 * 4)
#define B_KT_BYTES (B_BLK_B32 * 4)

__device__ __half2 g_A[(size_t)(MROWS / TM) * NKT * A_BLK_B32];   // 32MB
__device__ __half2 g_B[(size_t)(OUT_F / TN) * NKT * B_BLK_B32];   // 90MB

// ---------------- helpers ----------------
__device__ __forceinline__ uint32_t smem_u32(const void* p) {
    uint32_t a;
    asm("{ .reg .u64 t; cvta.to.shared.u64 t, %1; cvt.u32.u64 %0, t; }"
        : "=r"(a) : "l"(p));
    return a;
}
__device__ __forceinline__ void cp16(uint32_t dst, const void* src) {
    asm volatile("cp.async.cg.shared.global [%0], [%1], 16;"
                 :: "r"(dst), "l"(src) : "memory");
}
#define CP_COMMIT() asm volatile("cp.async.commit_group;" ::: "memory")
#define CP_WAIT1()  asm volatile("cp.async.wait_group 1;" ::: "memory")

__device__ __forceinline__ void mma_f16(float4& d, const uint4 a,
                                        const uint32_t b0, const uint32_t b1) {
    asm("mma.sync.aligned.m16n8k16.row.col.f32.f16.f16.f32 "
        "{%0,%1,%2,%3}, {%4,%5,%6,%7}, {%8,%9}, {%0,%1,%2,%3};"
        : "+f"(d.x), "+f"(d.y), "+f"(d.z), "+f"(d.w)
        : "r"(a.x), "r"(a.y), "r"(a.z), "r"(a.w), "r"(b0), "r"(b1));
}
__device__ __forceinline__ uint32_t h2u(__half2 h) { return *(uint32_t*)&h; }

// ---------------- prep: fragment-major pack, 1 thread = 1 16B chunk ------
__global__ void prep_x_kernel(const float* __restrict__ x,
                              const float* __restrict__ alpha) {
    int j = blockIdx.x * 256 + threadIdx.x;       // < MROWS*IN_F/8
    int blk = j >> 11, c = j & 2047;
    int th = c & 31, it = (c >> 5) & 15, s = c >> 9;
    int mb = blk >> 6, kt = blk & 63;
    int row0 = (mb << 8) + (it << 4) + (th >> 2);
    int k0 = (kt << 6) + (s << 4) + ((th & 3) << 1);
    const float* x0 = x + ((size_t)row0 << 12) + k0;
    const float* x8 = x0 + (8 << 12);
    float ia0 = 1.0f / alpha[k0],     ia1 = 1.0f / alpha[k0 + 1];
    float ia8 = 1.0f / alpha[k0 + 8], ia9 = 1.0f / alpha[k0 + 9];
    float2 v00 = *(const float2*)(x0);
    float2 v10 = *(const float2*)(x8);
    float2 v08 = *(const float2*)(x0 + 8);
    float2 v18 = *(const float2*)(x8 + 8);
    uint4 o;
    o.x = h2u(__floats2half2_rn(v00.x * ia0, v00.y * ia1));
    o.y = h2u(__floats2half2_rn(v10.x * ia0, v10.y * ia1));
    o.z = h2u(__floats2half2_rn(v08.x * ia8, v08.y * ia9));
    o.w = h2u(__floats2half2_rn(v18.x * ia8, v18.y * ia9));
    *(uint4*)(g_A + (size_t)j * 4) = o;
}

__global__ void prep_w_kernel(const int* __restrict__ q,
                              const float* __restrict__ sc) {
    int j = blockIdx.x * 256 + threadIdx.x;       // < OUT_F*IN_F/8
    int blk = j >> 10, c = j & 1023;
    int th = c & 31, jp = (c >> 5) & 7, s = c >> 8;
    int nb = blk >> 6, kt = blk & 63;
    int o0 = (nb << 7) + (jp << 4) + (th >> 2);
    int k0 = (kt << 6) + (s << 4) + ((th & 3) << 1);
    int sblk = (kt << 1) + (s >> 1);
    const int* q0 = q + ((size_t)o0 << 12) + k0;
    const int* q8 = q0 + (8 << 12);
    float s0 = sc[(o0 << 7) + sblk];
    float s1 = sc[((o0 + 8) << 7) + sblk];
    int2 a0 = *(const int2*)(q0);
    int2 a2 = *(const int2*)(q0 + 8);
    int2 b0 = *(const int2*)(q8);
    int2 b2 = *(const int2*)(q8 + 8);
    uint4 o;
    o.x = h2u(__floats2half2_rn((float)(a0.x - 8) * s0, (float)(a0.y - 8) * s0));
    o.y = h2u(__floats2half2_rn((float)(a2.x - 8) * s0, (float)(a2.y - 8) * s0));
    o.z = h2u(__floats2half2_rn((float)(b0.x - 8) * s1, (float)(b0.y - 8) * s1));
    o.w = h2u(__floats2half2_rn((float)(b2.x - 8) * s1, (float)(b2.y - 8) * s1));
    *(uint4*)(g_B + (size_t)j * 4) = o;
}

// ---------------- GEMM: 256x128 CTA, 8 warps (4x2) of 64x64 ----------------
__global__ __launch_bounds__(256, 1)
void awq_gemm_kernel(const float* __restrict__ bias, float* __restrict__ out) {
    extern __shared__ char sm[];
    const uint32_t sbase = smem_u32(sm);
    int tid = threadIdx.x, wid = tid >> 5, t = tid & 31;
    int wm = wid & 3, wn = wid >> 2;
    int mt = blockIdx.x, nt = blockIdx.y;

    const char* gA = (const char*)(g_A + (size_t)mt * NKT * A_BLK_B32);
    const char* gB = (const char*)(g_B + (size_t)nt * NKT * B_BLK_B32);

    const uint32_t cpoff = sbase + (uint32_t)tid * 16;
    auto copy_stage = [&](int kt, uint32_t pbase) {
        const char* srcA = gA + (size_t)kt * A_KT_BYTES + tid * 16;
#pragma unroll
        for (int r = 0; r < 8; r++)
            cp16(cpoff + pbase + r * 4096, srcA + r * 4096);
        const char* srcB = gB + (size_t)kt * B_KT_BYTES + tid * 16;
#pragma unroll
        for (int r = 0; r < 4; r++)
            cp16(cpoff + pbase + A_KT_BYTES + r * 4096, srcB + r * 4096);
    };

    copy_stage(0, 0); CP_COMMIT();
    copy_stage(1, STAGE_BYTES); CP_COMMIT();
    copy_stage(2, 2 * STAGE_BYTES); CP_COMMIT();

    float4 acc[4][8];
#pragma unroll
    for (int i = 0; i < 4; i++)
#pragma unroll
        for (int jj = 0; jj < 8; jj++) acc[i][jj] = make_float4(0.f, 0.f, 0.f, 0.f);

    // per-thread constant frag offsets within a stage
    const int aoff = wm * 2048 + t * 16;
    const int boff = A_KT_BYTES + wn * 2048 + t * 16;

    uint4 fa[2][4], fb[2][4];
    auto load_frag = [&](int bi, const char* stage, int s) {
        const char* ab = stage + s * 8192 + aoff;
        const char* bb = stage + s * 4096 + boff;
#pragma unroll
        for (int il = 0; il < 4; il++) fa[bi][il] = *(const uint4*)(ab + il * 512);
#pragma unroll
        for (int pl = 0; pl < 4; pl++) fb[bi][pl] = *(const uint4*)(bb + pl * 512);
    };
    auto do_mma = [&](int bi) {
#pragma unroll
        for (int il = 0; il < 4; il++)
#pragma unroll
            for (int jj = 0; jj < 8; jj++) {
                const uint4& bp = fb[bi][jj >> 1];
                if (jj & 1) mma_f16(acc[il][jj], fa[bi][il], bp.z, bp.w);
                else        mma_f16(acc[il][jj], fa[bi][il], bp.x, bp.y);
            }
    };

    // prologue: stages 0,1 arrived & visible; preload stage0 s0 frags
    CP_WAIT1();
    __syncthreads();
    load_frag(0, sm, 0);

    auto iter = [&](int kt, int p) {
        const char* stage = sm + (size_t)p * STAGE_BYTES;
        if (kt + 3 < NKT) copy_stage(kt + 3, (uint32_t)((p + 3) & 3) * STAGE_BYTES);
        CP_COMMIT();
#pragma unroll
        for (int s = 0; s < 4; s++) {
            int cur = s & 1;
            if (s < 3) load_frag(cur ^ 1, stage, s + 1);
            else if (kt + 1 < NKT)   // next stage's s0 (arrived last iter)
                load_frag(cur ^ 1, sm + (size_t)((p + 1) & 3) * STAGE_BYTES, 0);
            do_mma(cur);
        }
        CP_WAIT1();          // stage kt+2 arrived
        __syncthreads();     // publish cross-thread; protect slot reuse
    };

    for (int kt = 0; kt < NKT; kt += 4) {
        iter(kt + 0, 0);
        iter(kt + 1, 1);
        iter(kt + 2, 2);
        iter(kt + 3, 3);
    }

    // ---- epilogue ----
    int quad = t >> 2, tq = t & 3;
    int row_base = mt * TM + wm * 64;
    int col_base = nt * TN + wn * 64;
#pragma unroll
    for (int il = 0; il < 4; il++) {
        int r0 = row_base + il * 16 + quad;
        float* o0 = out + (size_t)r0 * OUT_F;
        float* o1 = o0 + (size_t)8 * OUT_F;
#pragma unroll
        for (int jj = 0; jj < 8; jj++) {
            int cc = col_base + jj * 8 + tq * 2;
            float2 bv = *(const float2*)(bias + cc);
            float4 v = acc[il][jj];
            *(float2*)(o0 + cc) = make_float2(v.x + bv.x, v.y + bv.y);
            *(float2*)(o1 + cc) = make_float2(v.z + bv.x, v.w + bv.y);
        }
    }
}

// ---------------- launch ----------------
extern "C" void kernel_launch(void* const* d_in, const int* in_sizes, int n_in,
                              void* d_out, int out_size) {
    const float* x     = (const float*)d_in[0];
    const int*   qw    = (const int*)d_in[1];
    const float* sc    = (const float*)d_in[2];
    const float* alpha = (const float*)d_in[3];
    const float* bias  = (const float*)d_in[4];
    float* out = (float*)d_out;

    cudaFuncSetAttribute(awq_gemm_kernel,
                         cudaFuncAttributeMaxDynamicSharedMemorySize, SMEM_BYTES);

    prep_x_kernel<<<(MROWS * IN_F) / 2048, 256>>>(x, alpha);
    prep_w_kernel<<<(OUT_F * IN_F) / 2048, 256>>>(qw, sc);

    dim3 grid(MROWS / TM, OUT_F / TN);            // (16, 86)
    awq_gemm_kernel<<<grid, 256, SMEM_BYTES>>>(bias, out);
}